// round 15
// baseline (speedup 1.0000x reference)
#include <cuda_runtime.h>
#include <cuda_fp16.h>
#include <math.h>
#include <stdint.h>

#define B_ 2
#define S_ 2048
#define E_ 1024
#define H_ 16
#define D_ 64
#define M_ (B_*S_)
#define QSCALE_ 0.18033688011112042f   // 0.125 * log2(e)

__device__ __half g_x [M_*E_];
__device__ __half g_wq[E_*E_];
__device__ __half g_wk[E_*E_];
__device__ __half g_wv[E_*E_];
__device__ __half g_wo[E_*E_];
__device__ __half g_q[B_*H_*S_*D_];
__device__ __half g_k[B_*H_*S_*D_];
__device__ __half g_v[B_*H_*S_*D_];
__device__ __half g_att[B_*S_*E_];

// ---------------------------------------------------------------------------
// helpers
// ---------------------------------------------------------------------------
__device__ __forceinline__ uint32_t packh2(float lo, float hi) {
    uint32_t r;
    asm("cvt.rn.f16x2.f32 %0, %1, %2;" : "=r"(r) : "f"(hi), "f"(lo));
    return r;
}

__device__ __forceinline__ uint32_t h2exp2(uint32_t x) {
    uint32_t r;
    asm("ex2.approx.f16x2 %0, %1;" : "=r"(r) : "r"(x));
    return r;
}

__device__ __forceinline__ void mma_f16(float c[4], const uint32_t a[4],
                                        uint32_t b0, uint32_t b1) {
    asm volatile(
        "mma.sync.aligned.m16n8k16.row.col.f32.f16.f16.f32 "
        "{%0,%1,%2,%3}, {%4,%5,%6,%7}, {%8,%9}, {%0,%1,%2,%3};"
        : "+f"(c[0]), "+f"(c[1]), "+f"(c[2]), "+f"(c[3])
        : "r"(a[0]), "r"(a[1]), "r"(a[2]), "r"(a[3]), "r"(b0), "r"(b1));
}

__device__ __forceinline__ void ldsm_x4(uint32_t& r0, uint32_t& r1,
                                        uint32_t& r2, uint32_t& r3,
                                        uint32_t addr) {
    asm volatile("ldmatrix.sync.aligned.m8n8.x4.shared.b16 {%0,%1,%2,%3}, [%4];"
                 : "=r"(r0), "=r"(r1), "=r"(r2), "=r"(r3) : "r"(addr));
}

__device__ __forceinline__ void ldsm_x4_t(uint32_t& r0, uint32_t& r1,
                                          uint32_t& r2, uint32_t& r3,
                                          uint32_t addr) {
    asm volatile("ldmatrix.sync.aligned.m8n8.x4.trans.shared.b16 {%0,%1,%2,%3}, [%4];"
                 : "=r"(r0), "=r"(r1), "=r"(r2), "=r"(r3) : "r"(addr));
}

__device__ __forceinline__ uint32_t s2u(const void* p) {
    uint32_t a;
    asm("{ .reg .u64 t; cvta.to.shared.u64 t, %1; cvt.u32.u64 %0, t; }"
        : "=r"(a) : "l"(p));
    return a;
}

__device__ __forceinline__ void cp16(uint32_t smem, const void* g) {
    asm volatile("cp.async.ca.shared.global [%0], [%1], 16;"
                 :: "r"(smem), "l"(g) : "memory");
}
#define CP_COMMIT() asm volatile("cp.async.commit_group;" ::: "memory")
#define CP_WAIT1()  asm volatile("cp.async.wait_group 1;" ::: "memory")
#define CP_WAIT0()  asm volatile("cp.async.wait_group 0;" ::: "memory")

// ---------------------------------------------------------------------------
// merged f32 -> f16 conversion
// ---------------------------------------------------------------------------
#define NX4 (M_ * E_ / 4)
#define NW4 (E_ * E_ / 4)
#define NTOT4 (NX4 + 4 * NW4)

__global__ void f2h_all_kernel(const float* __restrict__ x,
                               const float* __restrict__ wq,
                               const float* __restrict__ wk,
                               const float* __restrict__ wv,
                               const float* __restrict__ wo)
{
    int i = blockIdx.x * blockDim.x + threadIdx.x;
    if (i >= NTOT4) return;
    const float* src;
    __half* dst;
    int off;
    if (i < NX4) { src = x; dst = g_x; off = i; }
    else {
        int j = i - NX4;
        int sel = j / NW4;
        off = j - sel * NW4;
        src = (sel == 0) ? wq : (sel == 1) ? wk : (sel == 2) ? wv : wo;
        dst = (sel == 0) ? g_wq : (sel == 1) ? g_wk : (sel == 2) ? g_wv : g_wo;
    }
    float4 v = ((const float4*)src)[off];
    uint2 o;
    o.x = packh2(v.x, v.y);
    o.y = packh2(v.z, v.w);
    ((uint2*)dst)[off] = o;
}

// ---------------------------------------------------------------------------
// fp16 GEMM: BK=32 halves, 3-stage cp.async ring, one sync per k-tile.
// Block 128x128, 128 threads, 4 warps 2x2, warp tile 64x64.
// smem rows 20 words (16 data + 4 pad) -> ldmatrix conflict-free.
// 20.5KB/stage, 61.4KB total -> 3 CTAs/SM (12 warps).
// ---------------------------------------------------------------------------
#define GM 128
#define GN 128
#define GKH 32
#define GSTW 20
#define STAGE_W (GM * GSTW)                 // 2560 words per operand
#define NKT (E_ / GKH)                      // 32
#define GEMM_SMEM (3 * 2 * STAGE_W * 4)     // 61440 B

template<int MODE>
__global__ __launch_bounds__(128, 3)
void gemm_h_kernel(const __half* __restrict__ Ah,
                   const __half* __restrict__ Wq, const __half* __restrict__ Wk,
                   const __half* __restrict__ Wv,
                   __half* __restrict__ Cq, __half* __restrict__ Ck,
                   __half* __restrict__ Cv, float* __restrict__ Cf)
{
    extern __shared__ uint32_t dsm[];

    const __half* Wh = (MODE == 1) ? Wq
                     : (blockIdx.z == 0) ? Wq : (blockIdx.z == 1) ? Wk : Wv;
    __half* Ch = (blockIdx.z == 0) ? Cq : (blockIdx.z == 1) ? Ck : Cv;
    const float oscale = (MODE == 0 && blockIdx.z == 0) ? QSCALE_ : 1.0f;

    const int tid  = threadIdx.x;
    const int wid  = tid >> 5;
    const int lane = tid & 31;
    const int g    = lane >> 2;
    const int t    = lane & 3;
    const int wm   = (wid & 1) * 64;
    const int wn   = (wid >> 1) * 64;
    const int m0   = blockIdx.y * GM;
    const int n0   = blockIdx.x * GN;

    const uint32_t sbase = s2u(dsm);
    const uint32_t aoff = (((lane & 15) * GSTW) + ((lane >> 4) * 4)) * 4u;
    const uint32_t boff = ((((lane >> 4) * 8 + (lane & 7)) * GSTW)
                          + (((lane >> 3) & 1) * 4)) * 4u;

    const int crow = tid >> 2;     // 0..31
    const int cchk = tid & 3;      // 0..3 (16B chunks of 64B row)

    float acc[4][8][4];
    #pragma unroll
    for (int mi = 0; mi < 4; mi++)
        #pragma unroll
        for (int ni = 0; ni < 8; ni++)
            #pragma unroll
            for (int r = 0; r < 4; r++) acc[mi][ni][r] = 0.0f;

    auto issue = [&](int kt, int s) {
        const uint32_t sa = sbase + (uint32_t)(s * 2 * STAGE_W) * 4u;
        const uint32_t sw = sa + (uint32_t)STAGE_W * 4u;
        const __half* Agp = Ah + (size_t)(m0 + crow) * E_ + kt * GKH + cchk * 8;
        const __half* Wgp = Wh + (size_t)(n0 + crow) * E_ + kt * GKH + cchk * 8;
        #pragma unroll
        for (int i = 0; i < 4; i++) {
            const uint32_t so = (uint32_t)((crow + i * 32) * GSTW + cchk * 4) * 4u;
            cp16(sa + so, Agp + (size_t)(i * 32) * E_);
            cp16(sw + so, Wgp + (size_t)(i * 32) * E_);
        }
        CP_COMMIT();
    };

    issue(0, 0);
    issue(1, 1);

    for (int kt = 0; kt < NKT; kt++) {
        if (kt + 1 < NKT) { CP_WAIT1(); } else { CP_WAIT0(); }
        __syncthreads();
        if (kt + 2 < NKT) issue(kt + 2, (kt + 2) % 3);

        const int cs = kt % 3;
        const uint32_t bufA = sbase + (uint32_t)(cs * 2 * STAGE_W) * 4u;
        const uint32_t bufW = bufA + (uint32_t)STAGE_W * 4u;
        #pragma unroll
        for (int ks = 0; ks < 2; ks++) {
            const uint32_t kb = ks * 32u;          // 8 words = 16 halves
            uint32_t a[4][4];
            #pragma unroll
            for (int mi = 0; mi < 4; mi++)
                ldsm_x4(a[mi][0], a[mi][1], a[mi][2], a[mi][3],
                        bufA + aoff + (uint32_t)((wm + mi * 16) * GSTW) * 4u + kb);
            uint32_t b[8][2];
            #pragma unroll
            for (int pr = 0; pr < 4; pr++)
                ldsm_x4(b[2*pr][0], b[2*pr][1], b[2*pr+1][0], b[2*pr+1][1],
                        bufW + boff + (uint32_t)((wn + pr * 16) * GSTW) * 4u + kb);
            #pragma unroll
            for (int mi = 0; mi < 4; mi++)
                #pragma unroll
                for (int ni = 0; ni < 8; ni++)
                    mma_f16(acc[mi][ni], a[mi], b[ni][0], b[ni][1]);
        }
    }

    #pragma unroll
    for (int mi = 0; mi < 4; mi++) {
        #pragma unroll
        for (int ni = 0; ni < 8; ni++) {
            const int col = n0 + wn + ni * 8 + 2 * t;
            #pragma unroll
            for (int half = 0; half < 2; half++) {
                const int row = m0 + wm + mi * 16 + g + half * 8;
                if (MODE == 0) {
                    const int b = row >> 11;
                    const int s = row & (S_ - 1);
                    const int h = col >> 6;
                    const int d = col & (D_ - 1);
                    uint32_t hv = packh2(acc[mi][ni][half*2+0] * oscale,
                                         acc[mi][ni][half*2+1] * oscale);
                    *(uint32_t*)(Ch + ((size_t)(b * H_ + h) * S_ + s) * D_ + d) = hv;
                } else {
                    float2 v;
                    v.x = acc[mi][ni][half * 2 + 0];
                    v.y = acc[mi][ni][half * 2 + 1];
                    *(float2*)(Cf + (size_t)row * E_ + col) = v;
                }
            }
        }
    }
}

// ---------------------------------------------------------------------------
// fp16 flash attention (unchanged from R12 passing version).
// ---------------------------------------------------------------------------
#define AQT 128
#define AKT 64
#define AST 36
#define QW (AQT * AST)
#define KVW (AKT * AST)
#define STG_W (2 * KVW)
#define NT (S_ / AKT)
#define ATTN_SMEM ((QW + 3 * STG_W) * 4)
#define ONES2 0x3C003C00u

__global__ __launch_bounds__(256, 2)
void attn_f16_kernel()
{
    extern __shared__ uint32_t dsm[];

    const int tid  = threadIdx.x;
    const int w    = tid >> 5;
    const int lane = tid & 31;
    const int g    = lane >> 2;
    const int t    = lane & 3;
    const int bh   = blockIdx.y;
    const int q0   = blockIdx.x * AQT;
    const int qrow = q0 + w * 16;

    const uint32_t sbase = s2u(dsm);
    const uint32_t kvbase = sbase + (uint32_t)QW * 4u;
    const uint32_t aoffQ = (((w * 16 + (lane & 15)) * AST) + ((lane >> 4) * 4)) * 4u;
    const uint32_t boffK = ((((lane >> 4) * 8 + (lane & 7)) * AST)
                           + (((lane >> 3) & 1) * 4)) * 4u;
    const uint32_t voffV = (((lane & 15) * AST) + ((lane >> 4) * 4)) * 4u;

    const __half* Kb = g_k + (size_t)bh * S_ * D_;
    const __half* Vb = g_v + (size_t)bh * S_ * D_;
    const int crow = tid >> 3;
    const int cchk = tid & 7;

    auto issue = [&](int jt, int s) {
        const uint32_t sk = kvbase + (uint32_t)(s * STG_W) * 4u;
        const uint32_t sv = sk + (uint32_t)KVW * 4u;
        const __half* Kg = Kb + (size_t)(jt * AKT + crow) * D_ + cchk * 8;
        const __half* Vg = Vb + (size_t)(jt * AKT + crow) * D_ + cchk * 8;
        #pragma unroll
        for (int i = 0; i < 2; i++) {
            const uint32_t so = (uint32_t)((crow + i * 32) * AST + cchk * 4) * 4u;
            cp16(sk + so, Kg + (size_t)(i * 32) * D_);
            cp16(sv + so, Vg + (size_t)(i * 32) * D_);
        }
        CP_COMMIT();
    };

    {
        const uint4* Qg = (const uint4*)(g_q + ((size_t)bh * S_ + q0) * D_);
        #pragma unroll
        for (int i = 0; i < 4; i++) {
            const int idx = tid + i * 256;
            const int r = idx >> 3, c = idx & 7;
            *(uint4*)&dsm[r * AST + c * 4] = Qg[idx];
        }
    }
    issue(0, 0);
    issue(1, 1);
    __syncthreads();

    uint32_t aq[4][4];
    #pragma unroll
    for (int kc = 0; kc < 4; kc++)
        ldsm_x4(aq[kc][0], aq[kc][1], aq[kc][2], aq[kc][3],
                sbase + aoffQ + kc * 32u);

    float oacc[8][4];
    #pragma unroll
    for (int ni = 0; ni < 8; ni++)
        #pragma unroll
        for (int r = 0; r < 4; r++) oacc[ni][r] = 0.0f;
    float lacc[4] = {0.0f, 0.0f, 0.0f, 0.0f};

    float mA = -1e30f, mB = -1e30f;

    for (int jt = 0; jt < NT; jt++) {
        if (jt + 1 < NT) { CP_WAIT1(); } else { CP_WAIT0(); }
        __syncthreads();
        if (jt + 2 < NT) issue(jt + 2, (jt + 2) % 3);

        const int cs = jt % 3;
        const uint32_t baseK = kvbase + (uint32_t)(cs * STG_W) * 4u;
        const uint32_t baseV = baseK + (uint32_t)KVW * 4u;

        float sc[8][4];
        #pragma unroll
        for (int ni = 0; ni < 8; ni++)
            #pragma unroll
            for (int r = 0; r < 4; r++) sc[ni][r] = 0.0f;

        #pragma unroll
        for (int kc = 0; kc < 4; kc++) {
            const uint32_t kb = kc * 32u;
            #pragma unroll
            for (int pr = 0; pr < 4; pr++) {
                uint32_t b0, b1, b2, b3;
                ldsm_x4(b0, b1, b2, b3,
                        baseK + boffK + (uint32_t)(pr * 16 * AST) * 4u + kb);
                mma_f16(sc[2*pr],     aq[kc], b0, b1);
                mma_f16(sc[2*pr + 1], aq[kc], b2, b3);
            }
        }

        float rmA = -1e30f, rmB = -1e30f;
        #pragma unroll
        for (int ni = 0; ni < 8; ni++) {
            rmA = fmaxf(rmA, fmaxf(sc[ni][0], sc[ni][1]));
            rmB = fmaxf(rmB, fmaxf(sc[ni][2], sc[ni][3]));
        }
        rmA = fmaxf(rmA, __shfl_xor_sync(0xffffffffu, rmA, 1));
        rmA = fmaxf(rmA, __shfl_xor_sync(0xffffffffu, rmA, 2));
        rmB = fmaxf(rmB, __shfl_xor_sync(0xffffffffu, rmB, 1));
        rmB = fmaxf(rmB, __shfl_xor_sync(0xffffffffu, rmB, 2));

        const float nmA = fmaxf(mA, rmA);
        const float nmB = fmaxf(mB, rmB);
        const float cfA = exp2f(mA - nmA);
        const float cfB = exp2f(mB - nmB);
        mA = nmA; mB = nmB;

        lacc[0] *= cfA; lacc[1] *= cfA;
        lacc[2] *= cfB; lacc[3] *= cfB;
        #pragma unroll
        for (int ni = 0; ni < 8; ni++) {
            oacc[ni][0] *= cfA; oacc[ni][1] *= cfA;
            oacc[ni][2] *= cfB; oacc[ni][3] *= cfB;
        }

        #pragma unroll
        for (int kc = 0; kc < 4; kc++) {
            uint32_t ap[4];
            ap[0] = h2exp2(packh2(sc[2*kc][0]   - mA, sc[2*kc][1]   - mA));
            ap[1] = h2exp2(packh2(sc[2*kc][2]   - mB, sc[2*kc][3]   - mB));
            ap[2] = h2exp2(packh2(sc[2*kc+1][0] - mA, sc[2*kc+1][1] - mA));
            ap[3] = h2exp2(packh2(sc[2*kc+1][2] - mB, sc[2*kc+1][3] - mB));
            mma_f16(lacc, ap, ONES2, ONES2);
            const uint32_t krows = (uint32_t)(kc * 16 * AST) * 4u;
            #pragma unroll
            for (int npr = 0; npr < 4; npr++) {
                uint32_t b0, b1, b2, b3;
                ldsm_x4_t(b0, b1, b2, b3, baseV + voffV + krows + npr * 32u);
                mma_f16(oacc[2*npr],     ap, b0, b1);
                mma_f16(oacc[2*npr + 1], ap, b2, b3);
            }
        }
    }

    const float ivA = 1.0f / lacc[0];
    const float ivB = 1.0f / lacc[2];
    const int b = bh / H_;
    const int h = bh % H_;
    __half* OA = g_att + ((size_t)(b * S_ + qrow + g    ) * E_) + h * D_;
    __half* OB = g_att + ((size_t)(b * S_ + qrow + g + 8) * E_) + h * D_;
    #pragma unroll
    for (int ni = 0; ni < 8; ni++) {
        *(uint32_t*)(OA + ni * 8 + 2 * t) = packh2(oacc[ni][0] * ivA, oacc[ni][1] * ivA);
        *(uint32_t*)(OB + ni * 8 + 2 * t) = packh2(oacc[ni][2] * ivB, oacc[ni][3] * ivB);
    }
}

// ---------------------------------------------------------------------------
// Launch
// ---------------------------------------------------------------------------
extern "C" void kernel_launch(void* const* d_in, const int* in_sizes, int n_in,
                              void* d_out, int out_size)
{
    (void)in_sizes; (void)n_in; (void)out_size;
    const float* x  = (const float*)d_in[0];
    const float* wq = (const float*)d_in[1];
    const float* wk = (const float*)d_in[2];
    const float* wv = (const float*)d_in[3];
    const float* wo = (const float*)d_in[4];
    float* out = (float*)d_out;

    __half *px, *pwq, *pwk, *pwv, *pwo, *pq, *pk, *pv, *pa;
    cudaGetSymbolAddress((void**)&px,  g_x);
    cudaGetSymbolAddress((void**)&pwq, g_wq);
    cudaGetSymbolAddress((void**)&pwk, g_wk);
    cudaGetSymbolAddress((void**)&pwv, g_wv);
    cudaGetSymbolAddress((void**)&pwo, g_wo);
    cudaGetSymbolAddress((void**)&pq,  g_q);
    cudaGetSymbolAddress((void**)&pk,  g_k);
    cudaGetSymbolAddress((void**)&pv,  g_v);
    cudaGetSymbolAddress((void**)&pa,  g_att);

    f2h_all_kernel<<<(NTOT4 + 255) / 256, 256>>>(x, wq, wk, wv, wo);

    cudaFuncSetAttribute(gemm_h_kernel<0>,
                         cudaFuncAttributeMaxDynamicSharedMemorySize, GEMM_SMEM);
    cudaFuncSetAttribute(gemm_h_kernel<1>,
                         cudaFuncAttributeMaxDynamicSharedMemorySize, GEMM_SMEM);

    gemm_h_kernel<0><<<dim3(E_ / GN, M_ / GM, 3), 128, GEMM_SMEM>>>(
        px, pwq, pwk, pwv, pq, pk, pv, nullptr);

    cudaFuncSetAttribute(attn_f16_kernel,
                         cudaFuncAttributeMaxDynamicSharedMemorySize, ATTN_SMEM);
    attn_f16_kernel<<<dim3(S_ / AQT, B_ * H_), 256, ATTN_SMEM>>>();

    gemm_h_kernel<1><<<dim3(E_ / GN, M_ / GM, 1), 128, GEMM_SMEM>>>(
        pa, pwo, nullptr, nullptr, nullptr, nullptr, nullptr, out);
}